// round 13
// baseline (speedup 1.0000x reference)
#include <cuda_runtime.h>
#include <cstdint>

#define B_SZ   64
#define FEAT   512
#define NB     8
#define H_SZ   1024
#define WR     513            // W/2 + 1
#define HWR    (H_SZ * WR)    // 525312, divisible by 4
#define NQUAD  (HWR / 4)      // 131328
#define TPB    128
#define GRID   (NQUAD / TPB)  // 1026 exactly, single wave, all co-resident

// Handshake state (persists across graph replays; reset in-kernel).
__device__ float g_bw[B_SZ * NB];
__device__ int   g_ready;     // zero-init; producers release-add to 64
__device__ int   g_done;      // zero-init; blocks count to GRID

__device__ __forceinline__ int ld_acquire_gpu(const int* p) {
    int v;
    asm volatile("ld.acquire.gpu.global.s32 %0, [%1];" : "=r"(v) : "l"(p) : "memory");
    return v;
}
__device__ __forceinline__ void red_release_add(int* p, int v) {
    asm volatile("red.release.gpu.global.add.s32 [%0], %1;" :: "l"(p), "r"(v) : "memory");
}

// ---------------------------------------------------------------------------
// Fused kernel (R9 structure, store loop unroll 8).
//  Producers: blocks 0..63, block b = batch row b. One float4 feat load per
//    thread, w via __ldg float4, 8-band accumulators, warp shuffle + smem
//    reduce, 8-thread softmax, release-publish g_bw[b].
//  All blocks: 4 band indices (weight-independent, overlaps producers), then
//    acquire-spin on g_ready==64, load 64x9 LUT (slot 8 = 0 for r==max_r),
//    stream 64 float4 evict-first (__stcs) stores per thread.
//  Last block resets handshake for the next graph replay (after stores —
//  the ATOMG return must stay off the store-issue path, cf. R12 regression).
// ---------------------------------------------------------------------------
__global__ void __launch_bounds__(TPB) fused_freqmask_kernel(
        const float* __restrict__ feat,
        const float* __restrict__ wmat,
        const float* __restrict__ bias,
        float* __restrict__ out) {

    const int lane = threadIdx.x & 31;
    const int warp = threadIdx.x >> 5;

    __shared__ float pacc[4][NB];   // per-warp partial dots
    __shared__ float se[NB];

    // ---------------- producer: blocks 0..63, one block per batch row ------
    if (blockIdx.x < B_SZ) {
        const int b = blockIdx.x;
        const int k4 = threadIdx.x * 4;           // 512 = 128*4, one round
        float4 fv = *reinterpret_cast<const float4*>(feat + b * FEAT + k4);

        float acc[NB];
        #pragma unroll
        for (int i = 0; i < NB; i++) {
            float4 wv = __ldg(reinterpret_cast<const float4*>(wmat + i * FEAT + k4));
            acc[i] = fv.x * wv.x + fv.y * wv.y + fv.z * wv.z + fv.w * wv.w;
        }
        #pragma unroll
        for (int i = 0; i < NB; i++)
            #pragma unroll
            for (int o = 16; o; o >>= 1)
                acc[i] += __shfl_down_sync(0xffffffffu, acc[i], o);
        if (lane == 0)
            #pragma unroll
            for (int i = 0; i < NB; i++) pacc[warp][i] = acc[i];
        __syncthreads();

        if (threadIdx.x < NB) {
            int i = threadIdx.x;
            se[i] = pacc[0][i] + pacc[1][i] + pacc[2][i] + pacc[3][i] + bias[i];
        }
        __syncthreads();
        if (threadIdx.x < NB) {
            int i = threadIdx.x;
            float m = se[0];
            #pragma unroll
            for (int j = 1; j < NB; j++) m = fmaxf(m, se[j]);
            float e = expf(se[i] - m);
            float s = 0.0f;
            #pragma unroll
            for (int j = 0; j < NB; j++)
                s += __shfl_sync(0x000000ffu, e, j);
            g_bw[b * NB + i] = e / s;
        }
        __syncwarp(0xffffffffu);
        if (threadIdx.x == 0)
            red_release_add(&g_ready, 1);   // orders the 8 g_bw stores
    }

    // ---------------- band indices (independent of weights) ----------------
    const int base = (blockIdx.x * TPB + threadIdx.x) * 4;   // always < HWR
    const float max_r = sqrtf(0.5f);                          // bit-exact

    int band[4];
    #pragma unroll
    for (int j = 0; j < 4; j++) {
        int p  = base + j;
        int h  = p / WR;
        int wc = p - h * WR;
        float u = (float)wc * (1.0f / 1024.0f);
        float v = (float)(h < H_SZ / 2 ? h : h - H_SZ) * (1.0f / 1024.0f);
        float r = sqrtf(u * u + v * v);                       // exact args

        int bi = 0;
        #pragma unroll
        for (int i = 1; i < NB; i++)
            bi += (r >= max_r * ((float)i / (float)NB)) ? 1 : 0;
        band[j] = (r >= max_r) ? 8 : bi;                      // 8 -> zero slot
    }

    // ---------------- acquire-spin until all 64 rows published -------------
    if (threadIdx.x == 0) {
        while (ld_acquire_gpu(&g_ready) != B_SZ)
            __nanosleep(64);
    }
    __syncthreads();   // broadcasts the acquire to the whole block

    __shared__ float bw[B_SZ * 9];
    for (int i = threadIdx.x; i < B_SZ * 9; i += TPB) {
        int b = i / 9, s = i - b * 9;
        bw[i] = (s < NB) ? g_bw[b * NB + s] : 0.0f;
    }
    __syncthreads();

    // ---------------- streaming stores: 64 planes x float4, evict-first ----
    float* o = out + base;
    #pragma unroll 8
    for (int b = 0; b < B_SZ; b++) {
        const float* row = bw + b * 9;
        float4 v4;
        v4.x = row[band[0]];
        v4.y = row[band[1]];
        v4.z = row[band[2]];
        v4.w = row[band[3]];
        __stcs(reinterpret_cast<float4*>(o + (size_t)b * HWR), v4);
    }

    // ---------------- reset handshake for next graph replay ----------------
    __syncthreads();
    if (threadIdx.x == 0) {
        int d = atomicAdd(&g_done, 1);
        if (d == GRID - 1) {
            g_ready = 0;
            g_done  = 0;
        }
    }
}

// ---------------------------------------------------------------------------
extern "C" void kernel_launch(void* const* d_in, const int* in_sizes, int n_in,
                              void* d_out, int out_size) {
    const float* feat = (const float*)d_in[0];  // [64, 512]
    const float* w    = (const float*)d_in[1];  // [8, 512]
    const float* bias = (const float*)d_in[2];  // [8]
    float* out = (float*)d_out;                 // [64, 1, 1024, 513] fp32

    fused_freqmask_kernel<<<GRID, TPB>>>(feat, w, bias, out);
}

// round 14
// speedup vs baseline: 1.0581x; 1.0581x over previous
#include <cuda_runtime.h>

#define B_SZ   64
#define FEAT   512
#define NB     8
#define H_SZ   1024
#define WR     513            // W/2 + 1
#define HWR    (H_SZ * WR)    // 525312, divisible by 4
#define NQUAD  (HWR / 4)      // 131328
#define TPB    128
#define GRID   (NQUAD / TPB)  // 1026 exactly, single wave, all co-resident

// Handshake state (persists across graph replays; reset in-kernel).
__device__ float g_bw[B_SZ * NB];
__device__ int   g_ready;     // zero-init; producers release-add to 64
__device__ int   g_done;      // zero-init; blocks count to GRID

__device__ __forceinline__ int ld_acquire_gpu(const int* p) {
    int v;
    asm volatile("ld.acquire.gpu.global.s32 %0, [%1];" : "=r"(v) : "l"(p) : "memory");
    return v;
}
__device__ __forceinline__ void red_release_add(int* p, int v) {
    asm volatile("red.release.gpu.global.add.s32 [%0], %1;" :: "l"(p), "r"(v) : "memory");
}

// ---------------------------------------------------------------------------
// Fused kernel = R9: the measured optimum.
//  Producers: blocks 0..63, block b = batch row b. One float4 feat load per
//    thread, w via __ldg float4, 8-band accumulators, warp shuffle + smem
//    reduce, 8-thread softmax, release-publish g_bw[b].
//  All blocks: 4 band indices (weight-independent, overlaps producers), then
//    acquire-spin on g_ready==64, load 64x9 LUT (slot 8 = 0 for r==max_r),
//    stream 64 float4 evict-first (__stcs) stores per thread (unroll 4).
//  Last block resets handshake for the next graph replay.
// ---------------------------------------------------------------------------
__global__ void __launch_bounds__(TPB) fused_freqmask_kernel(
        const float* __restrict__ feat,
        const float* __restrict__ wmat,
        const float* __restrict__ bias,
        float* __restrict__ out) {

    const int lane = threadIdx.x & 31;
    const int warp = threadIdx.x >> 5;

    __shared__ float pacc[4][NB];   // per-warp partial dots
    __shared__ float se[NB];

    // ---------------- producer: blocks 0..63, one block per batch row ------
    if (blockIdx.x < B_SZ) {
        const int b = blockIdx.x;
        const int k4 = threadIdx.x * 4;           // 512 = 128*4, one round
        float4 fv = *reinterpret_cast<const float4*>(feat + b * FEAT + k4);

        float acc[NB];
        #pragma unroll
        for (int i = 0; i < NB; i++) {
            float4 wv = __ldg(reinterpret_cast<const float4*>(wmat + i * FEAT + k4));
            acc[i] = fv.x * wv.x + fv.y * wv.y + fv.z * wv.z + fv.w * wv.w;
        }
        #pragma unroll
        for (int i = 0; i < NB; i++)
            #pragma unroll
            for (int o = 16; o; o >>= 1)
                acc[i] += __shfl_down_sync(0xffffffffu, acc[i], o);
        if (lane == 0)
            #pragma unroll
            for (int i = 0; i < NB; i++) pacc[warp][i] = acc[i];
        __syncthreads();

        if (threadIdx.x < NB) {
            int i = threadIdx.x;
            se[i] = pacc[0][i] + pacc[1][i] + pacc[2][i] + pacc[3][i] + bias[i];
        }
        __syncthreads();
        if (threadIdx.x < NB) {
            int i = threadIdx.x;
            float m = se[0];
            #pragma unroll
            for (int j = 1; j < NB; j++) m = fmaxf(m, se[j]);
            float e = expf(se[i] - m);
            float s = 0.0f;
            #pragma unroll
            for (int j = 0; j < NB; j++)
                s += __shfl_sync(0x000000ffu, e, j);
            g_bw[b * NB + i] = e / s;
        }
        __syncwarp(0xffffffffu);
        if (threadIdx.x == 0)
            red_release_add(&g_ready, 1);   // orders the 8 g_bw stores
    }

    // ---------------- band indices (independent of weights) ----------------
    const int base = (blockIdx.x * TPB + threadIdx.x) * 4;   // always < HWR
    const float max_r = sqrtf(0.5f);                          // bit-exact

    int band[4];
    #pragma unroll
    for (int j = 0; j < 4; j++) {
        int p  = base + j;
        int h  = p / WR;
        int wc = p - h * WR;
        float u = (float)wc * (1.0f / 1024.0f);
        float v = (float)(h < H_SZ / 2 ? h : h - H_SZ) * (1.0f / 1024.0f);
        float r = sqrtf(u * u + v * v);                       // exact args

        int bi = 0;
        #pragma unroll
        for (int i = 1; i < NB; i++)
            bi += (r >= max_r * ((float)i / (float)NB)) ? 1 : 0;
        band[j] = (r >= max_r) ? 8 : bi;                      // 8 -> zero slot
    }

    // ---------------- acquire-spin until all 64 rows published -------------
    if (threadIdx.x == 0) {
        while (ld_acquire_gpu(&g_ready) != B_SZ)
            __nanosleep(64);
    }
    __syncthreads();   // broadcasts the acquire to the whole block

    __shared__ float bw[B_SZ * 9];
    for (int i = threadIdx.x; i < B_SZ * 9; i += TPB) {
        int b = i / 9, s = i - b * 9;
        bw[i] = (s < NB) ? g_bw[b * NB + s] : 0.0f;
    }
    __syncthreads();

    // ---------------- streaming stores: 64 planes x float4, evict-first ----
    float* o = out + base;
    #pragma unroll 4
    for (int b = 0; b < B_SZ; b++) {
        const float* row = bw + b * 9;
        float4 v4;
        v4.x = row[band[0]];
        v4.y = row[band[1]];
        v4.z = row[band[2]];
        v4.w = row[band[3]];
        __stcs(reinterpret_cast<float4*>(o + (size_t)b * HWR), v4);
    }

    // ---------------- reset handshake for next graph replay ----------------
    __syncthreads();
    if (threadIdx.x == 0) {
        int d = atomicAdd(&g_done, 1);
        if (d == GRID - 1) {
            g_ready = 0;
            g_done  = 0;
        }
    }
}

// ---------------------------------------------------------------------------
extern "C" void kernel_launch(void* const* d_in, const int* in_sizes, int n_in,
                              void* d_out, int out_size) {
    const float* feat = (const float*)d_in[0];  // [64, 512]
    const float* w    = (const float*)d_in[1];  // [8, 512]
    const float* bias = (const float*)d_in[2];  // [8]
    float* out = (float*)d_out;                 // [64, 1, 1024, 513] fp32

    fused_freqmask_kernel<<<GRID, TPB>>>(feat, w, bias, out);
}